// round 5
// baseline (speedup 1.0000x reference)
#include <cuda_runtime.h>
#include <cuda_bf16.h>

// ExperimentalLoss: multi-segment binary focal loss, HBM-bound streaming reduction.
// predictions/targets: (32, 8400, 720) fp32. Segments of D: 160/160/160/160/80
// with gammas 2.5/2.5/2.0/2.0/3.0. Output: scalar fp32.
//
// total = sum_seg [ sum_{b,p,d in seg} loss / (8400 * dims_seg) ]
// loss  = -( t*(1-p)^g*ln(p) + (1-t)*p^g*ln(1-p) ),  p clipped to [1e-7, 1-1e-7]

#define NBLOCKS  1184      // 148 SMs * 8
#define NTHREADS 256

__device__ float g_partials[NBLOCKS];

// MUFU EX2 directly via PTX (no device intrinsic named __exp2f exists).
__device__ __forceinline__ float fast_exp2(float x)
{
    float r;
    asm("ex2.approx.ftz.f32 %0, %1;" : "=f"(r) : "f"(x));
    return r;
}

// Per-float4 focal term (weighted, negated at accumulate site).
// Segment boundaries (in float4 units per 180-float4 row): 40/80/120/160/180.
__device__ __forceinline__ float focal4(float4 p, float4 t, unsigned int s)
{
    constexpr float EPS   = 1e-7f;
    constexpr float ONE_M = 1.0f - 1e-7f;

    float pe[4] = {p.x, p.y, p.z, p.w};
    float te[4] = {t.x, t.y, t.z, t.w};

    float term = 0.0f;
    #pragma unroll
    for (int j = 0; j < 4; j++) {
        float pp = fminf(fmaxf(pe[j], EPS), ONE_M);
        float q  = 1.0f - pp;
        float lg2p = __log2f(pp);   // MUFU LG2
        float lg2q = __log2f(q);    // MUFU LG2
        float pg, qg;
        if (s == 2u || s == 3u) {          // gamma = 2.0
            pg = pp * pp;
            qg = q * q;
        } else if (s == 4u) {              // gamma = 3.0
            pg = pp * pp * pp;
            qg = q * q * q;
        } else {                           // gamma = 2.5, reuse log2
            pg = fast_exp2(2.5f * lg2p);   // MUFU EX2
            qg = fast_exp2(2.5f * lg2q);
        }
        // loss_j = -( t*qg*ln(p) + (1-t)*pg*ln(q) );  ln(x) = lg2(x)*LN2
        term += te[j] * qg * lg2p + (1.0f - te[j]) * pg * lg2q;
    }
    return term;
}

__global__ __launch_bounds__(NTHREADS)
void focal_main_kernel(const float* __restrict__ pred,
                       const float* __restrict__ targ,
                       unsigned int n4)
{
    const float4* __restrict__ p4 = reinterpret_cast<const float4*>(pred);
    const float4* __restrict__ t4 = reinterpret_cast<const float4*>(targ);

    constexpr float LN2 = 0.69314718055994530942f;
    const float W160 = 1.0f / (8400.0f * 160.0f);
    const float W80  = 1.0f / (8400.0f * 80.0f);

    float acc0 = 0.0f, acc1 = 0.0f;
    const unsigned int stride = gridDim.x * blockDim.x;
    unsigned int idx = blockIdx.x * blockDim.x + threadIdx.x;

    // 2-way unroll: 4 outstanding LDG.128 per trip for MLP.
    for (; idx + stride < n4; idx += 2u * stride) {
        unsigned int i0 = idx;
        unsigned int i1 = idx + stride;
        unsigned int s0 = (i0 % 180u) / 40u;   // 0..4
        unsigned int s1 = (i1 % 180u) / 40u;

        float4 pa = __ldcs(p4 + i0);
        float4 ta = __ldcs(t4 + i0);
        float4 pb = __ldcs(p4 + i1);
        float4 tb = __ldcs(t4 + i1);

        float w0 = (s0 < 4u) ? W160 : W80;
        float w1 = (s1 < 4u) ? W160 : W80;
        acc0 = fmaf(-w0 * LN2, focal4(pa, ta, s0), acc0);
        acc1 = fmaf(-w1 * LN2, focal4(pb, tb, s1), acc1);
    }
    if (idx < n4) {
        unsigned int s = (idx % 180u) / 40u;
        float4 pa = __ldcs(p4 + idx);
        float4 ta = __ldcs(t4 + idx);
        float w = (s < 4u) ? W160 : W80;
        acc0 = fmaf(-w * LN2, focal4(pa, ta, s), acc0);
    }
    float acc = acc0 + acc1;

    // In-block reduction: warp shuffle, then one warp over the partials.
    __shared__ float sdata[NTHREADS / 32];
    unsigned int lane = threadIdx.x & 31u;
    unsigned int wid  = threadIdx.x >> 5;

    #pragma unroll
    for (int o = 16; o > 0; o >>= 1)
        acc += __shfl_down_sync(0xffffffffu, acc, o);
    if (lane == 0) sdata[wid] = acc;
    __syncthreads();

    if (wid == 0) {
        float v = (lane < NTHREADS / 32) ? sdata[lane] : 0.0f;
        #pragma unroll
        for (int o = 4; o > 0; o >>= 1)
            v += __shfl_down_sync(0xffffffffu, v, o);
        if (lane == 0) g_partials[blockIdx.x] = v;
    }
}

// Deterministic final reduction: fixed-order per-thread sums + tree.
__global__ __launch_bounds__(256)
void focal_final_kernel(float* __restrict__ out)
{
    __shared__ float s[256];
    float a = 0.0f;
    for (int i = threadIdx.x; i < NBLOCKS; i += 256)
        a += g_partials[i];
    s[threadIdx.x] = a;
    __syncthreads();
    #pragma unroll
    for (int ofs = 128; ofs > 0; ofs >>= 1) {
        if (threadIdx.x < (unsigned)ofs) s[threadIdx.x] += s[threadIdx.x + ofs];
        __syncthreads();
    }
    if (threadIdx.x == 0) out[0] = s[0];
}

extern "C" void kernel_launch(void* const* d_in, const int* in_sizes, int n_in,
                              void* d_out, int out_size)
{
    const float* pred = (const float*)d_in[0];
    const float* targ = (const float*)d_in[1];
    float* out = (float*)d_out;

    unsigned int n4 = (unsigned int)(in_sizes[0] / 4);  // 48,384,000 float4s

    focal_main_kernel<<<NBLOCKS, NTHREADS>>>(pred, targ, n4);
    focal_final_kernel<<<1, 256>>>(out);
}